// round 14
// baseline (speedup 1.0000x reference)
#include <cuda_runtime.h>
#include <cuda_fp16.h>
#include <cstdint>

// ImageWarped: trilinear sampling of [B,128,128,128,1] fp32 at [B,N,3] coords.
// B=2, N=2097152.
//
// R14 = R9 (best, 43.5us) + Programmatic Dependent Launch:
//   pack triggers launch-completion at block start; the sample kernel (with
//   the PSS launch attribute) dispatches while pack runs, executes its
//   pack-independent prologue (grid loads + coord math, the 48 MB stream),
//   then cudaGridDependencySynchronize() gates the scratch gathers on pack
//   completion. Moves sample's streaming wavefronts + DRAM into pack's
//   window and hides the second launch ramp.
//
// Pack: scalar 2x2x2 fp16 cube per voxel -> uint4 (evict-last L2 hint).
// Sample: ONE scattered 16B gather per sample (evict-last), 2 samples/
//   thread; grid/out evict-first streaming.
//
// fp16 quantization -> rel_err ~2.1e-4 (< 1e-3 gate, verified R3-R13).
// Out-of-range "+1" neighbors are weight-masked (exactly-zero fractional
// weights per the reference floor/ceil convention).

#define BATCH 2
#define NPTS  2097152
#define HVOX  (128 * 128 * 128)
#define VOXELS (BATCH * HVOX)
#define CLAMP_LO 0.001f
#define CLAMP_HI 126.999f

#define PACK_BLOCKS   (VOXELS / 256)            // 16384
#define SAMPLE_BLOCKS (BATCH * NPTS / 2 / 256)  // 8192 (2 samples/thread)

__device__ uint4 g_packed[VOXELS];              // 64 MB scratch

__device__ __forceinline__ uint32_t pack_h2(float a, float b) {
    __half2 h = __floats2half2_rn(a, b);
    return *reinterpret_cast<uint32_t*>(&h);
}

__device__ __forceinline__ uint64_t mk_evict_last_policy() {
    uint64_t pol;
    asm("createpolicy.fractional.L2::evict_last.b64 %0, 1.0;" : "=l"(pol));
    return pol;
}

__device__ __forceinline__ void st_hint_v4(uint4* p, uint4 v, uint64_t pol) {
    asm volatile("st.global.L2::cache_hint.v4.b32 [%0], {%1,%2,%3,%4}, %5;"
                 :: "l"(p), "r"(v.x), "r"(v.y), "r"(v.z), "r"(v.w), "l"(pol)
                 : "memory");
}

__device__ __forceinline__ uint4 ld_nc_hint_v4(const uint4* p, uint64_t pol) {
    uint4 v;
    asm volatile("ld.global.nc.L2::cache_hint.v4.b32 {%0,%1,%2,%3}, [%4], %5;"
                 : "=r"(v.x), "=r"(v.y), "=r"(v.z), "=r"(v.w)
                 : "l"(p), "l"(pol));
    return v;
}

__global__ void __launch_bounds__(256)
pack_kernel(const float* __restrict__ image)
{
    // Release the dependent sample launch immediately: its pre-sync prologue
    // (grid stream) overlaps this kernel.
    cudaTriggerProgrammaticLaunchCompletion();

    const uint64_t pol = mk_evict_last_policy();
    const int idx = blockIdx.x * blockDim.x + threadIdx.x;
    const int z = idx & 127;
    const int y = (idx >> 7) & 127;
    const int x = (idx >> 14) & 127;
    const int dz = (z < 127) ? 1 : 0;
    const int dy = (y < 127) ? 128 : 0;
    const int dx = (x < 127) ? 16384 : 0;

    const float c111 = __ldg(image + idx);
    const float c112 = __ldg(image + idx + dz);
    const float c121 = __ldg(image + idx + dy);
    const float c122 = __ldg(image + idx + dy + dz);
    const float c211 = __ldg(image + idx + dx);
    const float c212 = __ldg(image + idx + dx + dz);
    const float c221 = __ldg(image + idx + dx + dy);
    const float c222 = __ldg(image + idx + dx + dy + dz);

    uint4 p;
    p.x = pack_h2(c111, c112);
    p.y = pack_h2(c121, c122);
    p.z = pack_h2(c211, c212);
    p.w = pack_h2(c221, c222);
    st_hint_v4(&g_packed[idx], p, pol);
}

struct SampleIdx { int cube; float wx, wx2, wy, wy2, wz, wz2; };

__device__ __forceinline__ SampleIdx prep_one(float gx, float gy, float gz, int base_b)
{
    const float x = fminf(fmaxf(gx * 128.0f, CLAMP_LO), CLAMP_HI);
    const float y = fminf(fmaxf(gy * 128.0f, CLAMP_LO), CLAMP_HI);
    const float z = fminf(fmaxf(gz * 128.0f, CLAMP_LO), CLAMP_HI);

    const float x1f = floorf(x), x2f = ceilf(x);
    const float y1f = floorf(y), y2f = ceilf(y);
    const float z1f = floorf(z), z2f = ceilf(z);

    SampleIdx si;
    si.cube = base_b + (((int)x1f) << 14) + (((int)y1f) << 7) + (int)z1f;
    si.wx = x - x1f;  si.wx2 = x2f - x;
    si.wy = y - y1f;  si.wy2 = y2f - y;
    si.wz = z - z1f;  si.wz2 = z2f - z;
    return si;
}

__device__ __forceinline__ float finish_one(const SampleIdx& si, uint64_t pol)
{
    const uint4 p = ld_nc_hint_v4(&g_packed[si.cube], pol);

    const float2 a1 = __half22float2(*reinterpret_cast<const __half2*>(&p.x)); // c111,c112
    const float2 a2 = __half22float2(*reinterpret_cast<const __half2*>(&p.y)); // c121,c122
    const float2 b1 = __half22float2(*reinterpret_cast<const __half2*>(&p.z)); // c211,c212
    const float2 b2 = __half22float2(*reinterpret_cast<const __half2*>(&p.w)); // c221,c222

    const float lerp_y1 = (b1.x * si.wx + a1.x * si.wx2) * si.wy2
                        + (b2.x * si.wx + a2.x * si.wx2) * si.wy;
    const float lerp_y2 = (b1.y * si.wx + a1.y * si.wx2) * si.wy2
                        + (b2.y * si.wx + a2.y * si.wx2) * si.wy;
    return lerp_y2 * si.wz + lerp_y1 * si.wz2;
}

__global__ void __launch_bounds__(256)
trilinear_kernel(const float* __restrict__ grid,
                 float* __restrict__ out)
{
    const uint64_t pol = mk_evict_last_policy();
    const int t = blockIdx.x * blockDim.x + threadIdx.x;     // 2 samples/thread
    const int s = t << 1;
    const int base_b = (s >> 21) << 21;                      // batch base

    // ---- pack-independent prologue (overlaps pack via PDL) ----
    const float2* g = (const float2*)(grid + 3 * (size_t)s);
    const float2 q0 = __ldcs(g + 0);   // x0 y0
    const float2 q1 = __ldcs(g + 1);   // z0 x1
    const float2 q2 = __ldcs(g + 2);   // y1 z1

    const SampleIdx s0 = prep_one(q0.x, q0.y, q1.x, base_b);
    const SampleIdx s1 = prep_one(q1.y, q2.x, q2.y, base_b);

    // ---- wait for pack's scratch writes to be visible ----
    cudaGridDependencySynchronize();

    float2 r;
    r.x = finish_one(s0, pol);
    r.y = finish_one(s1, pol);
    __stcs((float2*)(out + s), r);
}

extern "C" void kernel_launch(void* const* d_in, const int* in_sizes, int n_in,
                              void* d_out, int out_size)
{
    const float* image = (const float*)d_in[0];
    const float* grid  = (const float*)d_in[1];
    float* out = (float*)d_out;

    pack_kernel<<<PACK_BLOCKS, 256>>>(image);

    cudaLaunchConfig_t cfg = {};
    cfg.gridDim  = dim3(SAMPLE_BLOCKS, 1, 1);
    cfg.blockDim = dim3(256, 1, 1);
    cudaLaunchAttribute attr[1];
    attr[0].id = cudaLaunchAttributeProgrammaticStreamSerialization;
    attr[0].val.programmaticStreamSerializationAllowed = 1;
    cfg.attrs = attr;
    cfg.numAttrs = 1;
    cudaLaunchKernelEx(&cfg, trilinear_kernel, grid, out);
}